// round 9
// baseline (speedup 1.0000x reference)
#include <cuda_runtime.h>
#include <cuda_fp16.h>
#include <cstdint>

// MTLSTM: B=128, T=512, K=12, H=256, OUT=1
// Persistent kernel: 128 CTAs x 256 threads, fp16 mma.m16n8k16.
// Fragment-native fp16 state layout; exchange via per-(half,k-quarter) release
// counters + per-warp cp.async.cg staging with mbarrier completion.

#define NB 128
#define NT 512
#define NKF 12
#define GRID 128
#define THREADS 256

// State layout (halves): buf:65536, s(h=0,c=1):32768, mh:16384, mpos:8192,
// ch:512, mt:256, gq:32, tq:8, hi:4, rlo:2, lo:1
__device__ __half g_S[2 * 65536];
__device__ float g_dec[NB * NT * NKF];     // (1/ln(e+dt) - 1)
__device__ unsigned g_cnt[2][4][32];       // per (half, k-quarter) arrival counter
__device__ unsigned g_bar0;                // init barrier

// ---------------- PTX helpers ----------------
__device__ __forceinline__ uint32_t smem_u32(const void* p) {
    return (uint32_t)__cvta_generic_to_shared(p);
}
__device__ __forceinline__ void mbar_init(uint32_t a, uint32_t cnt) {
    asm volatile("mbarrier.init.shared.b64 [%0], %1;" :: "r"(a), "r"(cnt) : "memory");
}
__device__ __forceinline__ void mbar_wait(uint32_t a, uint32_t parity) {
    asm volatile(
        "{\n\t.reg .pred P;\n\t"
        "W%=: mbarrier.try_wait.parity.acquire.cta.shared::cta.b64 P, [%0], %1, 0x989680;\n\t"
        "@P bra D%=;\n\t"
        "bra W%=;\n\t"
        "D%=:\n\t}"
        :: "r"(a), "r"(parity) : "memory");
}
__device__ __forceinline__ void cp16(uint32_t dst, const void* src) {
    asm volatile("cp.async.cg.shared.global [%0], [%1], 16;\n" :: "r"(dst), "l"(src));
}
__device__ __forceinline__ void cp_arrive(uint32_t mbar) {
    asm volatile("cp.async.mbarrier.arrive.noinc.shared.b64 [%0];" :: "r"(mbar) : "memory");
}
__device__ __forceinline__ unsigned ld_acq(const unsigned* p) {
    unsigned v;
    asm volatile("ld.acquire.gpu.global.u32 %0, [%1];" : "=r"(v) : "l"(p) : "memory");
    return v;
}
__device__ __forceinline__ void red_release_add(unsigned* p, unsigned v) {
    asm volatile("red.release.gpu.global.add.u32 [%0], %1;" :: "l"(p), "r"(v) : "memory");
}
__device__ __forceinline__ void mma_f16(float acc[4],
                                        uint32_t a0, uint32_t a1, uint32_t a2, uint32_t a3,
                                        uint32_t b0, uint32_t b1) {
    asm volatile(
        "mma.sync.aligned.m16n8k16.row.col.f32.f16.f16.f32 "
        "{%0,%1,%2,%3}, {%4,%5,%6,%7}, {%8,%9}, {%0,%1,%2,%3};\n"
        : "+f"(acc[0]), "+f"(acc[1]), "+f"(acc[2]), "+f"(acc[3])
        : "r"(a0), "r"(a1), "r"(a2), "r"(a3), "r"(b0), "r"(b1));
}
__device__ __forceinline__ float tanha(float x) {
    float r;
    asm("tanh.approx.f32 %0, %1;" : "=f"(r) : "f"(x));
    return r;
}
__device__ __forceinline__ float siga(float x) {
    return fmaf(tanha(0.5f * x), 0.5f, 0.5f);
}

// ---- smem byte layout ----
#define SM_MBAR   0                       // 4 mbarriers
#define SM_A      128                     // 65536B staged state
#define SM_CSM    (SM_A + 65536)          // 64*66 floats
#define SM_WIH    (SM_CSM + 64 * 66 * 4)
#define SM_BIAS   (SM_WIH + 192 * 4)
#define SM_BDE    (SM_BIAS + 16 * 4)
#define SM_TOTAL  (SM_BDE + 48 * 4)

__global__ void __launch_bounds__(THREADS, 1)
mtlstm_persistent(const float* __restrict__ xd, const float* __restrict__ dtp,
                  const float* __restrict__ Wih, const float* __restrict__ Whh,
                  const float* __restrict__ bias, const float* __restrict__ Wd,
                  const float* __restrict__ bde, const float* __restrict__ lw,
                  const float* __restrict__ lb, float* __restrict__ out) {
    extern __shared__ unsigned char smraw[];
    const __half* sA = reinterpret_cast<const __half*>(smraw + SM_A);
    float* Csm = reinterpret_cast<float*>(smraw + SM_CSM);
    float* sWih = reinterpret_cast<float*>(smraw + SM_WIH);
    float* sBias = reinterpret_cast<float*>(smraw + SM_BIAS);
    float* sBde = reinterpret_cast<float*>(smraw + SM_BDE);
    const uint32_t smbase = smem_u32(smraw);

    const int tid = threadIdx.x;
    const int mh = blockIdx.x & 1;        // batch half this CTA computes
    const int ns = blockIdx.x >> 1;       // o-slice
    const int o0 = ns * 4;

    if (tid == 0) {
#pragma unroll
        for (int i = 0; i < 4; ++i) mbar_init(smbase + SM_MBAR + 8 * i, 256);
    }

    // ---- small tables ----
    if (tid < 16) {
        int g = tid >> 2, ol = tid & 3;
        sBias[tid] = bias[g * 256 + o0 + ol];
        for (int k = 0; k < NKF; ++k)
            sWih[tid * NKF + k] = Wih[(g * 256 + o0 + ol) * NKF + k];
    }
    if (tid < 48) {
        int kf = tid >> 2, ol = tid & 3;
        sBde[tid] = bde[kf * 256 + o0 + ol];
    }

    // ---- precompute decay-1 (once, cooperatively) ----
    {
        const int gt = blockIdx.x * THREADS + tid;
        const int total = NB * NT * NKF;
        for (int i = gt; i < total; i += GRID * THREADS) {
            float v = dtp[i];
            g_dec[i] = 1.0f / __logf(2.71828182845904523536f + v) - 1.0f;
        }
    }

    // ---- warp / lane mapping ----
    const int w = tid >> 5;
    const int lane = tid & 31;
    const int gq = lane >> 2;
    const int tq = lane & 3;
    const int mpos = w >> 2;        // consumer row group
    const int npos = w & 3;         // 0 -> gates (A=h), 1..3 -> decomp (A=c)
    const int s_w = (npos == 0) ? 0 : 1;
    // staging region owned by this warp: (s_r, mp_r, hf)
    const int s_r = w >> 2;
    const int mp_r = (w >> 1) & 1;
    const int hf = w & 1;

    // ---- B weight fragments into registers (once) ----
    uint32_t breg[64];              // [nt(2)][ch(16)][2]
#pragma unroll
    for (int nt = 0; nt < 2; ++nt) {
        const int ntile = npos * 2 + nt;
        const int ncol = ntile * 8 + gq;
        const float* row;
        if (ncol < 16) {
            int g = ncol >> 2, ol = ncol & 3;
            row = Whh + (size_t)(g * 256 + o0 + ol) * 256;
        } else {
            int idx = ncol - 16;
            int kf = idx >> 2, ol = idx & 3;
            row = Wd + (size_t)(kf * 256 + o0 + ol) * 256;
        }
#pragma unroll
        for (int ch = 0; ch < 16; ++ch) {
            const int c0 = ch * 16 + 2 * tq;
            __half2 p0 = __floats2half2_rn(row[c0], row[c0 + 1]);
            __half2 p1 = __floats2half2_rn(row[c0 + 8], row[c0 + 9]);
            breg[(nt * 16 + ch) * 2]     = *reinterpret_cast<uint32_t*>(&p0);
            breg[(nt * 16 + ch) * 2 + 1] = *reinterpret_cast<uint32_t*>(&p1);
        }
    }

    // consumer A base in smem (halves)
    const __half* awarp = sA + s_w * 16384 + mpos * 8192 + gq * 32 + tq * 8;
    // staging bases (halves)
    const int stage_off = s_r * 16384 + mp_r * 8192 + hf * 1024 + lane * 8;
    const uint32_t sdst0 = smbase + SM_A + stage_off * 2;
    const __half* gsrc0 = g_S + s_r * 32768 + (size_t)mh * 16384 + mp_r * 8192 +
                          hf * 1024 + lane * 8;

    // ---- epilogue mapping ----
    const int eb = tid >> 2;
    const int eol = tid & 3;
    const int gb = mh * 64 + eb;
    const int go = o0 + eol;
    const int woff = mh * 16384 + (eb >> 5) * 8192 + (go >> 4) * 512 +
                     (((eb >> 3) & 3) >> 1) * 256 + (eb & 7) * 32 +
                     (((go & 15) >> 1) & 3) * 8 + ((go & 15) >> 3) * 4 +
                     (((eb >> 3) & 1)) * 2 + (go & 1);
    const float* xrow_base = xd + (size_t)gb * NT * NKF;
    const float* dec_base = g_dec + (size_t)gb * NT * NKF;
    float c_reg = 0.0f;

    // ---- init barrier: g_dec, tables, mbarriers visible ----
    __threadfence();
    __syncthreads();
    if (tid == 0) {
        atomicAdd(&g_bar0, 1u);
        while (*(volatile unsigned*)&g_bar0 < (unsigned)GRID) { }
        __threadfence();
    }
    __syncthreads();

    for (int t = 0; t < NT; ++t) {
        const int p = t & 1;        // read buffer p, write 1-p

        // ---- prefetch x, dec + hoisted x-part of gate preactivations ----
        float preX[4], d[12];
        {
            const float* xrow = xrow_base + (size_t)t * NKF;
            const float* drow = dec_base + (size_t)t * NKF;
            float x[12];
            float4 x0 = reinterpret_cast<const float4*>(xrow)[0];
            float4 x1 = reinterpret_cast<const float4*>(xrow)[1];
            float4 x2 = reinterpret_cast<const float4*>(xrow)[2];
            x[0] = x0.x; x[1] = x0.y; x[2] = x0.z; x[3] = x0.w;
            x[4] = x1.x; x[5] = x1.y; x[6] = x1.z; x[7] = x1.w;
            x[8] = x2.x; x[9] = x2.y; x[10] = x2.z; x[11] = x2.w;
            float4 d0 = reinterpret_cast<const float4*>(drow)[0];
            float4 d1 = reinterpret_cast<const float4*>(drow)[1];
            float4 d2 = reinterpret_cast<const float4*>(drow)[2];
            d[0] = d0.x; d[1] = d0.y; d[2] = d0.z; d[3] = d0.w;
            d[4] = d1.x; d[5] = d1.y; d[6] = d1.z; d[7] = d1.w;
            d[8] = d2.x; d[9] = d2.y; d[10] = d2.z; d[11] = d2.w;
#pragma unroll
            for (int g = 0; g < 4; ++g) {
                float s = sBias[g * 4 + eol];
                const float* wr = &sWih[(g * 4 + eol) * NKF];
#pragma unroll
                for (int k = 0; k < NKF; ++k) s += x[k] * wr[k];
                preX[g] = s;
            }
        }

        float acc[2][2][4];
#pragma unroll
        for (int a = 0; a < 2; ++a)
#pragma unroll
            for (int b = 0; b < 2; ++b)
#pragma unroll
                for (int c = 0; c < 4; ++c) acc[a][b][c] = 0.0f;

        if (t > 0) {
            const unsigned tgt = 16u * (unsigned)t;
            const uint32_t par = (uint32_t)((t - 1) & 1);
            const __half* gsrc = gsrc0 + (size_t)p * 65536;

            // poll + stage quarter 0
            {
                if (lane == 0)
                    while (ld_acq(&g_cnt[mh][0][0]) < tgt) { }
                __syncwarp();
                (void)ld_acq(&g_cnt[mh][0][0]);
#pragma unroll
                for (int i = 0; i < 4; ++i)
                    cp16(sdst0 + i * 512, gsrc + i * 256);
                cp_arrive(smbase + SM_MBAR);
            }
#pragma unroll
            for (int chq = 0; chq < 4; ++chq) {
                if (chq < 3) {
                    const int q = chq + 1;
                    if (lane == 0)
                        while (ld_acq(&g_cnt[mh][q][0]) < tgt) { }
                    __syncwarp();
                    (void)ld_acq(&g_cnt[mh][q][0]);
#pragma unroll
                    for (int i = 0; i < 4; ++i)
                        cp16(sdst0 + (q * 2048 + i * 256) * 2, gsrc + q * 2048 + i * 256);
                    cp_arrive(smbase + SM_MBAR + 8 * q);
                }
                mbar_wait(smbase + SM_MBAR + 8 * chq, par);
#pragma unroll
                for (int c4 = 0; c4 < 4; ++c4) {
                    const int ch = chq * 4 + c4;
                    uint4 va = *reinterpret_cast<const uint4*>(awarp + ch * 512);
                    uint4 vb = *reinterpret_cast<const uint4*>(awarp + ch * 512 + 256);
#pragma unroll
                    for (int nt = 0; nt < 2; ++nt) {
                        mma_f16(acc[0][nt], va.x, va.y, va.z, va.w,
                                breg[(nt * 16 + ch) * 2], breg[(nt * 16 + ch) * 2 + 1]);
                        mma_f16(acc[1][nt], vb.x, vb.y, vb.z, vb.w,
                                breg[(nt * 16 + ch) * 2], breg[(nt * 16 + ch) * 2 + 1]);
                    }
                }
            }
        }

        // ---- dump accumulators to Csm ----
#pragma unroll
        for (int mt = 0; mt < 2; ++mt)
#pragma unroll
            for (int nt = 0; nt < 2; ++nt) {
                const int ntile = npos * 2 + nt;
                const int col0 = ntile * 8 + 2 * tq;
                const int rr = mpos * 32 + mt * 16 + gq;
                *reinterpret_cast<float2*>(&Csm[rr * 66 + col0]) =
                    make_float2(acc[mt][nt][0], acc[mt][nt][1]);
                *reinterpret_cast<float2*>(&Csm[(rr + 8) * 66 + col0]) =
                    make_float2(acc[mt][nt][2], acc[mt][nt][3]);
            }
        __syncthreads();

        // ---- epilogue ----
        {
            float ig = siga(preX[0] + Csm[eb * 66 + 0 + eol]);
            float fg = siga(preX[1] + Csm[eb * 66 + 4 + eol]);
            float gg = tanha(preX[2] + Csm[eb * 66 + 8 + eol]);
            float og = siga(preX[3] + Csm[eb * 66 + 12 + eol]);

            float S = 0.0f;
#pragma unroll
            for (int k = 0; k < NKF; ++k) {
                float cs = tanha(Csm[eb * 66 + 16 + k * 4 + eol] + sBde[k * 4 + eol]);
                S += cs * d[k];
            }

            float cn = fg * (c_reg + S) + ig * gg;
            c_reg = cn;
            float hn = og * tanha(cn);
            __half* gdst = g_S + (size_t)(1 - p) * 65536 + woff;
            gdst[0] = __float2half_rn(hn);        // s=0 (h)
            gdst[32768] = __float2half_rn(cn);    // s=1 (c)
        }

        // ---- publish: release-arrive on this CTA's k-quarter counter ----
        __syncthreads();
        if (tid == 0) red_release_add(&g_cnt[mh][ns >> 4][0], 1u);
    }

    // ---- final: wait for the half we OUTPUT (row b), then dot with lw ----
    {
        const int omh = blockIdx.x >> 6;        // half containing output row b
        if (tid < 4) {
            const unsigned tgt = 16u * (unsigned)NT;
            while (ld_acq(&g_cnt[omh][tid][0]) < tgt) { }
        }
        __syncthreads();

        if (w == 0) {
            const int b = blockIdx.x;
            const int r = b & 63;
            const int rpart = omh * 16384 + (r >> 5) * 8192 +
                              (((r >> 3) & 3) >> 1) * 256 + (r & 7) * 32 +
                              ((r >> 3) & 1) * 2;
            float ssum = 0.0f;
            for (int dd = lane; dd < 256; dd += 32) {
                const int kk = dd & 15;
                const int off = rpart + (dd >> 4) * 512 + ((kk >> 1) & 3) * 8 +
                                (kk >> 3) * 4 + (kk & 1);
                ssum += __half2float(g_S[off]) * lw[dd];   // buf 0 (step 511), s=0
            }
#pragma unroll
            for (int off = 16; off; off >>= 1)
                ssum += __shfl_xor_sync(0xffffffffu, ssum, off);
            if (lane == 0) out[b] = ssum + lb[0];
        }
    }
}

__global__ void mtlstm_barzero() {
    g_bar0 = 0u;
    for (int h = 0; h < 2; ++h)
        for (int q = 0; q < 4; ++q)
            for (int i = 0; i < 32; ++i) g_cnt[h][q][i] = 0u;
}

extern "C" void kernel_launch(void* const* d_in, const int* in_sizes, int n_in,
                              void* d_out, int out_size) {
    const float* xd  = (const float*)d_in[0];
    const float* dtp = (const float*)d_in[1];
    const float* wih = (const float*)d_in[2];
    const float* whh = (const float*)d_in[3];
    const float* bia = (const float*)d_in[4];
    const float* wd  = (const float*)d_in[5];
    const float* bde = (const float*)d_in[6];
    const float* lw  = (const float*)d_in[7];
    const float* lb  = (const float*)d_in[8];
    float* out = (float*)d_out;

    cudaFuncSetAttribute(mtlstm_persistent,
                         cudaFuncAttributeMaxDynamicSharedMemorySize, SM_TOTAL);

    mtlstm_barzero<<<1, 1>>>();
    mtlstm_persistent<<<GRID, THREADS, SM_TOTAL>>>(xd, dtp, wih, whh, bia, wd,
                                                   bde, lw, lb, out);
}

// round 10
// speedup vs baseline: 1.5336x; 1.5336x over previous
#include <cuda_runtime.h>
#include <cuda_fp16.h>
#include <cstdint>

// MTLSTM: B=128, T=512, K=12, H=256, OUT=1
// Persistent kernel: 128 CTAs x 256 threads, fp16 mma.m16n8k16.
// Fragment-native fp16 state layout; R8-style exchange (tid0 poller + bulk TMA
// + mbarriers) with release/acquire publication; cheap approx epilogue.

#define NB 128
#define NT 512
#define NKF 12
#define GRID 128
#define THREADS 256

// State layout (halves): buf:65536, s(h=0,c=1):32768, mh:16384, mpos:8192,
// ch:512, mt:256, gq:32, tq:8, hi:4, rlo:2, lo:1
__device__ __half g_S[2 * 65536];
__device__ float g_dec[NB * NT * NKF];   // (1/ln(e+dt) - 1)
__device__ unsigned g_barh[2][32];       // per-half step barrier (separate lines)
__device__ unsigned g_bar0;              // init barrier

// ---------------- PTX helpers ----------------
__device__ __forceinline__ uint32_t smem_u32(const void* p) {
    return (uint32_t)__cvta_generic_to_shared(p);
}
__device__ __forceinline__ void mbar_init(uint32_t a, uint32_t cnt) {
    asm volatile("mbarrier.init.shared.b64 [%0], %1;" :: "r"(a), "r"(cnt) : "memory");
}
__device__ __forceinline__ void mbar_expect_tx(uint32_t a, uint32_t bytes) {
    asm volatile("mbarrier.arrive.expect_tx.shared.b64 _, [%0], %1;"
                 :: "r"(a), "r"(bytes) : "memory");
}
__device__ __forceinline__ void mbar_wait(uint32_t a, uint32_t parity) {
    asm volatile(
        "{\n\t.reg .pred P;\n\t"
        "W%=: mbarrier.try_wait.parity.acquire.cta.shared::cta.b64 P, [%0], %1, 0x989680;\n\t"
        "@P bra D%=;\n\t"
        "bra W%=;\n\t"
        "D%=:\n\t}"
        :: "r"(a), "r"(parity) : "memory");
}
__device__ __forceinline__ void bulk_g2s(uint32_t dst, const void* src,
                                         uint32_t bytes, uint32_t mbar) {
    asm volatile(
        "cp.async.bulk.shared::cluster.global.mbarrier::complete_tx::bytes "
        "[%0], [%1], %2, [%3];"
        :: "r"(dst), "l"(src), "r"(bytes), "r"(mbar) : "memory");
}
__device__ __forceinline__ unsigned ld_acq(const unsigned* p) {
    unsigned v;
    asm volatile("ld.acquire.gpu.global.u32 %0, [%1];" : "=r"(v) : "l"(p) : "memory");
    return v;
}
__device__ __forceinline__ void red_release_add(unsigned* p, unsigned v) {
    asm volatile("red.release.gpu.global.add.u32 [%0], %1;" :: "l"(p), "r"(v) : "memory");
}
__device__ __forceinline__ void mma_f16(float acc[4],
                                        uint32_t a0, uint32_t a1, uint32_t a2, uint32_t a3,
                                        uint32_t b0, uint32_t b1) {
    asm volatile(
        "mma.sync.aligned.m16n8k16.row.col.f32.f16.f16.f32 "
        "{%0,%1,%2,%3}, {%4,%5,%6,%7}, {%8,%9}, {%0,%1,%2,%3};\n"
        : "+f"(acc[0]), "+f"(acc[1]), "+f"(acc[2]), "+f"(acc[3])
        : "r"(a0), "r"(a1), "r"(a2), "r"(a3), "r"(b0), "r"(b1));
}
__device__ __forceinline__ float tanha(float x) {
    float r;
    asm("tanh.approx.f32 %0, %1;" : "=f"(r) : "f"(x));
    return r;
}
__device__ __forceinline__ float siga(float x) {
    return fmaf(tanha(0.5f * x), 0.5f, 0.5f);
}

// ---- smem byte layout ----
#define SM_MBAR   0                      // 16 mbarriers
#define SM_A      128                    // 65536B staged state
#define SM_CSM    (SM_A + 65536)         // 64*66 floats
#define SM_WIH    (SM_CSM + 64 * 66 * 4)
#define SM_BIAS   (SM_WIH + 192 * 4)
#define SM_BDE    (SM_BIAS + 16 * 4)
#define SM_TOTAL  (SM_BDE + 48 * 4)

__global__ void __launch_bounds__(THREADS, 1)
mtlstm_persistent(const float* __restrict__ xd, const float* __restrict__ dtp,
                  const float* __restrict__ Wih, const float* __restrict__ Whh,
                  const float* __restrict__ bias, const float* __restrict__ Wd,
                  const float* __restrict__ bde, const float* __restrict__ lw,
                  const float* __restrict__ lb, float* __restrict__ out) {
    extern __shared__ unsigned char smraw[];
    const __half* sA = reinterpret_cast<const __half*>(smraw + SM_A);
    float* Csm = reinterpret_cast<float*>(smraw + SM_CSM);
    float* sWih = reinterpret_cast<float*>(smraw + SM_WIH);
    float* sBias = reinterpret_cast<float*>(smraw + SM_BIAS);
    float* sBde = reinterpret_cast<float*>(smraw + SM_BDE);
    const uint32_t smbase = smem_u32(smraw);

    const int tid = threadIdx.x;
    const int mh = blockIdx.x & 1;       // batch half
    const int ns = blockIdx.x >> 1;      // o-slice
    const int o0 = ns * 4;

    if (tid == 0) {
#pragma unroll
        for (int i = 0; i < 16; ++i) mbar_init(smbase + SM_MBAR + 8 * i, 1);
    }

    // ---- small tables ----
    if (tid < 16) {
        int g = tid >> 2, ol = tid & 3;
        sBias[tid] = bias[g * 256 + o0 + ol];
        for (int k = 0; k < NKF; ++k)
            sWih[tid * NKF + k] = Wih[(g * 256 + o0 + ol) * NKF + k];
    }
    if (tid < 48) {
        int kf = tid >> 2, ol = tid & 3;
        sBde[tid] = bde[kf * 256 + o0 + ol];
    }

    // ---- precompute decay-1 (once, cooperatively) ----
    {
        const int gt = blockIdx.x * THREADS + tid;
        const int total = NB * NT * NKF;
        for (int i = gt; i < total; i += GRID * THREADS) {
            float v = dtp[i];
            g_dec[i] = 1.0f / __logf(2.71828182845904523536f + v) - 1.0f;
        }
    }

    // ---- warp / lane mapping ----
    const int w = tid >> 5;
    const int lane = tid & 31;
    const int gq = lane >> 2;
    const int tq = lane & 3;
    const int mpos = w >> 2;       // 0..1
    const int npos = w & 3;        // 0 -> gates (A=h), 1..3 -> decomp (A=c)
    const int s_w = (npos == 0) ? 0 : 1;

    // ---- B weight fragments into registers (once) ----
    uint32_t breg[64];             // [nt(2)][ch(16)][2]
#pragma unroll
    for (int nt = 0; nt < 2; ++nt) {
        const int ntile = npos * 2 + nt;
        const int ncol = ntile * 8 + gq;
        const float* row;
        if (ncol < 16) {
            int g = ncol >> 2, ol = ncol & 3;
            row = Whh + (size_t)(g * 256 + o0 + ol) * 256;
        } else {
            int idx = ncol - 16;
            int kf = idx >> 2, ol = idx & 3;
            row = Wd + (size_t)(kf * 256 + o0 + ol) * 256;
        }
#pragma unroll
        for (int ch = 0; ch < 16; ++ch) {
            const int c0 = ch * 16 + 2 * tq;
            __half2 p0 = __floats2half2_rn(row[c0], row[c0 + 1]);
            __half2 p1 = __floats2half2_rn(row[c0 + 8], row[c0 + 9]);
            breg[(nt * 16 + ch) * 2]     = *reinterpret_cast<uint32_t*>(&p0);
            breg[(nt * 16 + ch) * 2 + 1] = *reinterpret_cast<uint32_t*>(&p1);
        }
    }

    // per-warp A base in smem (halves)
    const __half* awarp = sA + s_w * 16384 + mpos * 8192 + gq * 32 + tq * 8;
    const uint32_t my_mbar0 = smbase + SM_MBAR + 8 * ((s_w * 2 + mpos) * 4);

    // ---- epilogue mapping ----
    const int eb = tid >> 2;
    const int eol = tid & 3;
    const int gb = mh * 64 + eb;
    const int go = o0 + eol;
    const int woff = mh * 16384 + (eb >> 5) * 8192 + (go >> 4) * 512 +
                     (((eb >> 3) & 3) >> 1) * 256 + (eb & 7) * 32 +
                     (((go & 15) >> 1) & 3) * 8 + ((go & 15) >> 3) * 4 +
                     (((eb >> 3) & 1)) * 2 + (go & 1);
    const float* xrow_base = xd + (size_t)gb * NT * NKF;
    const float* dec_base = g_dec + (size_t)gb * NT * NKF;
    float c_reg = 0.0f;

    unsigned* barh = &g_barh[mh][0];

    // ---- init barrier: g_dec, tables, mbarriers visible ----
    __threadfence();
    __syncthreads();
    if (tid == 0) {
        atomicAdd(&g_bar0, 1u);
        while (*(volatile unsigned*)&g_bar0 < (unsigned)GRID) { }
        __threadfence();
    }
    __syncthreads();

    for (int t = 0; t < NT; ++t) {
        const int p = t & 1;       // read buffer p, write 1-p

        // ---- prefetch x, dec + hoisted x-part of gate preactivations ----
        float preX[4], d[12];
        {
            const float* xrow = xrow_base + (size_t)t * NKF;
            const float* drow = dec_base + (size_t)t * NKF;
            float x[12];
            float4 x0 = reinterpret_cast<const float4*>(xrow)[0];
            float4 x1 = reinterpret_cast<const float4*>(xrow)[1];
            float4 x2 = reinterpret_cast<const float4*>(xrow)[2];
            x[0] = x0.x; x[1] = x0.y; x[2] = x0.z; x[3] = x0.w;
            x[4] = x1.x; x[5] = x1.y; x[6] = x1.z; x[7] = x1.w;
            x[8] = x2.x; x[9] = x2.y; x[10] = x2.z; x[11] = x2.w;
            float4 d0 = reinterpret_cast<const float4*>(drow)[0];
            float4 d1 = reinterpret_cast<const float4*>(drow)[1];
            float4 d2 = reinterpret_cast<const float4*>(drow)[2];
            d[0] = d0.x; d[1] = d0.y; d[2] = d0.z; d[3] = d0.w;
            d[4] = d1.x; d[5] = d1.y; d[6] = d1.z; d[7] = d1.w;
            d[8] = d2.x; d[9] = d2.y; d[10] = d2.z; d[11] = d2.w;
#pragma unroll
            for (int g = 0; g < 4; ++g) {
                float s = sBias[g * 4 + eol];
                const float* wr = &sWih[(g * 4 + eol) * NKF];
#pragma unroll
                for (int k = 0; k < NKF; ++k) s += x[k] * wr[k];
                preX[g] = s;
            }
        }

        float acc[2][2][4];
#pragma unroll
        for (int a = 0; a < 2; ++a)
#pragma unroll
            for (int b = 0; b < 2; ++b)
#pragma unroll
                for (int c = 0; c < 4; ++c) acc[a][b][c] = 0.0f;

        if (t > 0) {
            // tid0: wait for all CTAs of this half, then issue bulk TMAs
            if (tid == 0) {
                const unsigned target = (unsigned)t * (GRID / 2);
                while (ld_acq(barh) < target) { }
                const __half* gsrc = g_S + (size_t)p * 65536 + mh * 16384;
#pragma unroll
                for (int chq = 0; chq < 4; ++chq) {
#pragma unroll
                    for (int s = 1; s >= 0; --s) {       // c first (6 of 8 warps)
#pragma unroll
                        for (int mp = 0; mp < 2; ++mp) {
                            uint32_t mb = smbase + SM_MBAR + 8 * ((s * 2 + mp) * 4 + chq);
                            mbar_expect_tx(mb, 4096);
                            bulk_g2s(smbase + SM_A + (s * 16384 + mp * 8192 + chq * 2048) * 2,
                                     gsrc + s * 32768 + mp * 8192 + chq * 2048, 4096, mb);
                        }
                    }
                }
            }
            const uint32_t par = (uint32_t)((t - 1) & 1);
#pragma unroll
            for (int chq = 0; chq < 4; ++chq) {
                mbar_wait(my_mbar0 + 8 * chq, par);
#pragma unroll
                for (int c4 = 0; c4 < 4; ++c4) {
                    const int ch = chq * 4 + c4;
                    uint4 va = *reinterpret_cast<const uint4*>(awarp + ch * 512);
                    uint4 vb = *reinterpret_cast<const uint4*>(awarp + ch * 512 + 256);
#pragma unroll
                    for (int nt = 0; nt < 2; ++nt) {
                        mma_f16(acc[0][nt], va.x, va.y, va.z, va.w,
                                breg[(nt * 16 + ch) * 2], breg[(nt * 16 + ch) * 2 + 1]);
                        mma_f16(acc[1][nt], vb.x, vb.y, vb.z, vb.w,
                                breg[(nt * 16 + ch) * 2], breg[(nt * 16 + ch) * 2 + 1]);
                    }
                }
            }
        }

        // ---- dump accumulators to Csm ----
#pragma unroll
        for (int mt = 0; mt < 2; ++mt)
#pragma unroll
            for (int nt = 0; nt < 2; ++nt) {
                const int ntile = npos * 2 + nt;
                const int col0 = ntile * 8 + 2 * tq;
                const int rr = mpos * 32 + mt * 16 + gq;
                *reinterpret_cast<float2*>(&Csm[rr * 66 + col0]) =
                    make_float2(acc[mt][nt][0], acc[mt][nt][1]);
                *reinterpret_cast<float2*>(&Csm[(rr + 8) * 66 + col0]) =
                    make_float2(acc[mt][nt][2], acc[mt][nt][3]);
            }
        __syncthreads();

        // ---- epilogue ----
        {
            float ig = siga(preX[0] + Csm[eb * 66 + 0 + eol]);
            float fg = siga(preX[1] + Csm[eb * 66 + 4 + eol]);
            float gg = tanha(preX[2] + Csm[eb * 66 + 8 + eol]);
            float og = siga(preX[3] + Csm[eb * 66 + 12 + eol]);

            float S = 0.0f;
#pragma unroll
            for (int k = 0; k < NKF; ++k) {
                float cs = tanha(Csm[eb * 66 + 16 + k * 4 + eol] + sBde[k * 4 + eol]);
                S += cs * d[k];
            }

            float cn = fg * (c_reg + S) + ig * gg;
            c_reg = cn;
            float hn = og * tanha(cn);
            __half* gdst = g_S + (size_t)(1 - p) * 65536 + woff;
            gdst[0] = __float2half_rn(hn);        // s=0 (h)
            gdst[32768] = __float2half_rn(cn);    // s=1 (c)
        }

        // ---- publish: CTA-wide sync, then single release-arrive ----
        __syncthreads();
        if (tid == 0) red_release_add(barh, 1u);
    }

    // ---- final: wait for the half we OUTPUT (row b = blockIdx.x) ----
    {
        const int omh = blockIdx.x >> 6;     // half containing output row b
        if (tid == 0) {
            const unsigned tgt = (unsigned)NT * (GRID / 2);
            while (ld_acq(&g_barh[omh][0]) < tgt) { }
        }
        __syncthreads();

        if (w == 0) {
            const int b = blockIdx.x;
            const int r = b & 63;
            const int rpart = omh * 16384 + (r >> 5) * 8192 +
                              (((r >> 3) & 3) >> 1) * 256 + (r & 7) * 32 +
                              ((r >> 3) & 1) * 2;
            float ssum = 0.0f;
            for (int dd = lane; dd < 256; dd += 32) {
                const int kk = dd & 15;
                const int off = rpart + (dd >> 4) * 512 + ((kk >> 1) & 3) * 8 +
                                (kk >> 3) * 4 + (kk & 1);
                ssum += __half2float(g_S[off]) * lw[dd];   // buf 0 (step 511), s=0
            }
#pragma unroll
            for (int off = 16; off; off >>= 1)
                ssum += __shfl_xor_sync(0xffffffffu, ssum, off);
            if (lane == 0) out[b] = ssum + lb[0];
        }
    }
}

__global__ void mtlstm_barzero() {
    g_bar0 = 0u;
    g_barh[0][0] = 0u;
    g_barh[1][0] = 0u;
}

extern "C" void kernel_launch(void* const* d_in, const int* in_sizes, int n_in,
                              void* d_out, int out_size) {
    const float* xd  = (const float*)d_in[0];
    const float* dtp = (const float*)d_in[1];
    const float* wih = (const float*)d_in[2];
    const float* whh = (const float*)d_in[3];
    const float* bia = (const float*)d_in[4];
    const float* wd  = (const float*)d_in[5];
    const float* bde = (const float*)d_in[6];
    const float* lw  = (const float*)d_in[7];
    const float* lb  = (const float*)d_in[8];
    float* out = (float*)d_out;

    cudaFuncSetAttribute(mtlstm_persistent,
                         cudaFuncAttributeMaxDynamicSharedMemorySize, SM_TOTAL);

    mtlstm_barzero<<<1, 1>>>();
    mtlstm_persistent<<<GRID, THREADS, SM_TOTAL>>>(xd, dtp, wih, whh, bia, wd,
                                                   bde, lw, lb, out);
}